// round 9
// baseline (speedup 1.0000x reference)
#include <cuda_runtime.h>
#include <cuda_bf16.h>
#include <cstdint>
#include <cstddef>

// ---------------------------------------------------------------------------
// CTLSTM: B=64, L=512, I=256, H=256, G=7H=1792
// Outputs: 6 planes, each (B, L+1, H) fp32, concatenated in d_out:
//   [h_decayed, h, c, c_bar, o, d]
// ---------------------------------------------------------------------------

constexpr int Bb = 64;
constexpr int Ll = 512;
constexpr int Ii = 256;
constexpr int Hh = 256;
constexpr int Gg = 7 * Hh;                 // 1792
constexpr int NCTA = 128;                  // scan grid (co-resident, <=148 SMs)
constexpr size_t S_OUT = (size_t)Bb * (Ll + 1) * Hh;   // 8,404,992

// SMEM layout for the scan kernel (dynamic): Wh slice + h tile, both padded.
constexpr int WPAD = 260;                  // 256 + 4 floats padding
constexpr int SCAN_SMEM = (56 * WPAD + 16 * WPAD) * 4; // 74,880 B

// Device scratch (no allocation allowed)
__device__ float    g_xg[(size_t)Bb * Ll * Gg];   // 224 MB
__device__ float    g_h[2][Bb * Hh];              // h double buffer
__device__ unsigned g_cnt[Ll];                    // per-step barrier counters

// ---------------------------------------------------------------------------
// Init: zero barrier counters, h0, and the t=0 output rows (d_out is poisoned)
// ---------------------------------------------------------------------------
__global__ void init_kernel(float* __restrict__ out) {
    int i = blockIdx.x * blockDim.x + threadIdx.x;
    if (i < Ll) g_cnt[i] = 0u;
    if (i < Bb * Hh) g_h[0][i] = 0.0f;
    if (i < 6 * Bb * Hh) {
        int o = i / (Bb * Hh);
        int r = i % (Bb * Hh);
        int b = r >> 8;
        int j = r & 255;
        out[(size_t)o * S_OUT + (size_t)b * (Ll + 1) * Hh + j] = 0.0f;
    }
}

// ---------------------------------------------------------------------------
// Phase A: g_xg[m][g] = sum_k x[m][k] * Wx[g][k] + bx[g]
// M=32768, N=1792, K=256. 128x128 tiles, BK=16, double buffered, 8x8 micro.
// ---------------------------------------------------------------------------
__global__ __launch_bounds__(256) void xg_gemm(const float* __restrict__ X,
                                               const float* __restrict__ W,
                                               const float* __restrict__ bx) {
    __shared__ float As[2][16][128];
    __shared__ float Bs[2][16][128];

    const int tid = threadIdx.x;
    const int tx  = tid & 15;
    const int ty  = tid >> 4;
    const int n0  = blockIdx.x * 128;
    const int m0  = blockIdx.y * 128;

    const int r0 = tid >> 2;   // 0..63
    const int r1 = r0 + 64;    // 64..127
    const int c4 = tid & 3;    // float4 index within a 16-wide k chunk

    float acc[8][8];
#pragma unroll
    for (int i = 0; i < 8; ++i)
#pragma unroll
        for (int j = 0; j < 8; ++j) acc[i][j] = 0.0f;

    const float4* Xr0 = (const float4*)(X + (size_t)(m0 + r0) * Ii);
    const float4* Xr1 = (const float4*)(X + (size_t)(m0 + r1) * Ii);
    const float4* Wr0 = (const float4*)(W + (size_t)(n0 + r0) * Ii);
    const float4* Wr1 = (const float4*)(W + (size_t)(n0 + r1) * Ii);

    // preload kt = 0
    {
        float4 v0 = __ldg(Xr0 + c4);
        float4 v1 = __ldg(Xr1 + c4);
        float4 w0 = __ldg(Wr0 + c4);
        float4 w1 = __ldg(Wr1 + c4);
        As[0][c4 * 4 + 0][r0] = v0.x; As[0][c4 * 4 + 1][r0] = v0.y;
        As[0][c4 * 4 + 2][r0] = v0.z; As[0][c4 * 4 + 3][r0] = v0.w;
        As[0][c4 * 4 + 0][r1] = v1.x; As[0][c4 * 4 + 1][r1] = v1.y;
        As[0][c4 * 4 + 2][r1] = v1.z; As[0][c4 * 4 + 3][r1] = v1.w;
        Bs[0][c4 * 4 + 0][r0] = w0.x; Bs[0][c4 * 4 + 1][r0] = w0.y;
        Bs[0][c4 * 4 + 2][r0] = w0.z; Bs[0][c4 * 4 + 3][r0] = w0.w;
        Bs[0][c4 * 4 + 0][r1] = w1.x; Bs[0][c4 * 4 + 1][r1] = w1.y;
        Bs[0][c4 * 4 + 2][r1] = w1.z; Bs[0][c4 * 4 + 3][r1] = w1.w;
    }
    __syncthreads();

    int buf = 0;
    for (int kt = 0; kt < 16; ++kt) {
        float4 pv0, pv1, pw0, pw1;
        if (kt < 15) {
            int f4 = (kt + 1) * 4 + c4;
            pv0 = __ldg(Xr0 + f4);
            pv1 = __ldg(Xr1 + f4);
            pw0 = __ldg(Wr0 + f4);
            pw1 = __ldg(Wr1 + f4);
        }
#pragma unroll
        for (int kk = 0; kk < 16; ++kk) {
            float4 a0 = *(const float4*)&As[buf][kk][ty * 8];
            float4 a1 = *(const float4*)&As[buf][kk][ty * 8 + 4];
            float4 b0 = *(const float4*)&Bs[buf][kk][tx * 8];
            float4 b1 = *(const float4*)&Bs[buf][kk][tx * 8 + 4];
            float av[8] = {a0.x, a0.y, a0.z, a0.w, a1.x, a1.y, a1.z, a1.w};
            float bv[8] = {b0.x, b0.y, b0.z, b0.w, b1.x, b1.y, b1.z, b1.w};
#pragma unroll
            for (int i = 0; i < 8; ++i)
#pragma unroll
                for (int j = 0; j < 8; ++j)
                    acc[i][j] = fmaf(av[i], bv[j], acc[i][j]);
        }
        if (kt < 15) {
            int nb = buf ^ 1;
            As[nb][c4 * 4 + 0][r0] = pv0.x; As[nb][c4 * 4 + 1][r0] = pv0.y;
            As[nb][c4 * 4 + 2][r0] = pv0.z; As[nb][c4 * 4 + 3][r0] = pv0.w;
            As[nb][c4 * 4 + 0][r1] = pv1.x; As[nb][c4 * 4 + 1][r1] = pv1.y;
            As[nb][c4 * 4 + 2][r1] = pv1.z; As[nb][c4 * 4 + 3][r1] = pv1.w;
            Bs[nb][c4 * 4 + 0][r0] = pw0.x; Bs[nb][c4 * 4 + 1][r0] = pw0.y;
            Bs[nb][c4 * 4 + 2][r0] = pw0.z; Bs[nb][c4 * 4 + 3][r0] = pw0.w;
            Bs[nb][c4 * 4 + 0][r1] = pw1.x; Bs[nb][c4 * 4 + 1][r1] = pw1.y;
            Bs[nb][c4 * 4 + 2][r1] = pw1.z; Bs[nb][c4 * 4 + 3][r1] = pw1.w;
        }
        __syncthreads();
        buf ^= 1;
    }

    float bxr[8];
#pragma unroll
    for (int j = 0; j < 8; ++j) bxr[j] = __ldg(bx + n0 + tx * 8 + j);

#pragma unroll
    for (int i = 0; i < 8; ++i) {
        size_t row = (size_t)(m0 + ty * 8 + i);
        float4 o0, o1;
        o0.x = acc[i][0] + bxr[0]; o0.y = acc[i][1] + bxr[1];
        o0.z = acc[i][2] + bxr[2]; o0.w = acc[i][3] + bxr[3];
        o1.x = acc[i][4] + bxr[4]; o1.y = acc[i][5] + bxr[5];
        o1.z = acc[i][6] + bxr[6]; o1.w = acc[i][7] + bxr[7];
        float4* cp = (float4*)(g_xg + row * Gg + n0 + tx * 8);
        cp[0] = o0;
        cp[1] = o1;
    }
}

// ---------------------------------------------------------------------------
// Scan helpers
// ---------------------------------------------------------------------------
__device__ __forceinline__ float sigmoidf_(float x) {
    return 1.0f / (1.0f + __expf(-x));
}
__device__ __forceinline__ float softplusf_(float x) {
    return (x > 20.0f) ? x : log1pf(__expf(x));
}

// ---------------------------------------------------------------------------
// Scan: 128 persistent CTAs x 128 threads. CTA = (16 batches) x (8 hidden j).
// Thread = one (b, j): 7 gate dot products over k=256, elementwise local.
// Wh slice (56 rows, padded stride 260) stays in SMEM for all 512 steps.
// ---------------------------------------------------------------------------
__global__ __launch_bounds__(128) void scan_kernel(
    const float* __restrict__ dt,        // (B, L)
    const int*   __restrict__ seq_lens,  // (B,)
    const float* __restrict__ Wh,        // (1792, 256)
    const float* __restrict__ bh,        // (1792,)
    float*       __restrict__ out)
{
    extern __shared__ float smem[];
    float* whs = smem;                 // [56][WPAD]
    float* hs  = smem + 56 * WPAD;     // [16][WPAD]

    const int tid  = threadIdx.x;
    const int cta  = blockIdx.x;
    const int jblk = cta & 31;         // 32 j-blocks of 8
    const int bblk = cta >> 5;         // 4 b-blocks of 16
    const int bi   = tid >> 3;         // 0..15
    const int ji   = tid & 7;          // 0..7
    const int b    = bblk * 16 + bi;
    const int j    = jblk * 8 + ji;

    // Load the 56-row Wh slice into SMEM (rows g*256 + jblk*8 + jj).
    for (int idx = tid; idx < 56 * 64; idx += 128) {
        int row = idx >> 6;            // 0..55
        int cf  = idx & 63;            // float4 within row
        int g   = row >> 3;
        int jj  = row & 7;
        float4 v = __ldg((const float4*)(Wh + (size_t)(g * 256 + jblk * 8 + jj) * 256) + cf);
        *(float4*)(whs + row * WPAD + cf * 4) = v;
    }

    float bhr[7];
#pragma unroll
    for (int g = 0; g < 7; ++g) bhr[g] = __ldg(bh + g * 256 + j);

    const int my_len = __ldg(seq_lens + b);
    const int wmax   = __reduce_max_sync(0xffffffffu, my_len);

    const float* hp  = hs + bi * WPAD;
    const float* wpb = whs + ji * WPAD;

    float cprev = 0.0f;

    for (int t = 0; t < Ll; ++t) {
        const int cur = t & 1;
        const int nxt = cur ^ 1;

        // Load h tile (16 x 256) from g_h[cur] -> hs. Must bypass L1 (__ldcg):
        // the same addresses recur every other step and L1 is not coherent.
        {
            const float4* src = (const float4*)(g_h[cur] + bblk * 16 * 256);
#pragma unroll
            for (int i = 0; i < 8; ++i) {
                int idx = tid + i * 128;           // 0..1023
                int row = idx >> 6;
                int cf  = idx & 63;
                float4 v = __ldcg(src + row * 64 + cf);
                *(float4*)(hs + row * WPAD + cf * 4) = v;
            }
        }

        // Prefetch xg gates + dt for this step (hidden under the dot product).
        float xgv[7] = {0, 0, 0, 0, 0, 0, 0};
        float dtv = 0.0f;
        if (t < wmax) {
            const float* xp = g_xg + ((size_t)b * Ll + t) * Gg + j;
#pragma unroll
            for (int g = 0; g < 7; ++g) xgv[g] = __ldg(xp + g * 256);
            dtv = __ldg(dt + b * Ll + t);
        }

        __syncthreads();   // hs visible

        float acc[7] = {0, 0, 0, 0, 0, 0, 0};
        if (t < wmax) {
#pragma unroll 2
            for (int k = 0; k < 256; k += 4) {
                const float4 hv = *(const float4*)(hp + k);
#pragma unroll
                for (int g = 0; g < 7; ++g) {
                    const float4 wv = *(const float4*)(wpb + g * (8 * WPAD) + k);
                    acc[g] = fmaf(hv.x, wv.x, acc[g]);
                    acc[g] = fmaf(hv.y, wv.y, acc[g]);
                    acc[g] = fmaf(hv.z, wv.z, acc[g]);
                    acc[g] = fmaf(hv.w, wv.w, acc[g]);
                }
            }
        }

        // Gates. split order: i, f, z, o, d, ib, fb
        float gi = acc[0] + xgv[0] + bhr[0];
        float gf = acc[1] + xgv[1] + bhr[1];
        float gz = acc[2] + xgv[2] + bhr[2];
        float go = acc[3] + xgv[3] + bhr[3];
        float gd = acc[4] + xgv[4] + bhr[4];
        float gib = acc[5] + xgv[5] + bhr[5];
        float gfb = acc[6] + xgv[6] + bhr[6];

        float iv  = sigmoidf_(gi);
        float fv  = sigmoidf_(gf);
        float zv  = tanhf(gz);
        float ov  = sigmoidf_(go);
        float dv  = softplusf_(gd);
        float ibv = sigmoidf_(gib);
        float fbv = sigmoidf_(gfb);

        float cfull = fv * cprev + iv * zv;
        float hfull = ov * tanhf(cfull);
        float cb    = fbv * cprev + ibv * zv;
        float ct    = cb + (cfull - cb) * __expf(-dv * dtv);
        float ht    = ov * tanhf(ct);

        if (t >= my_len) {             // masked: outputs and carry are zero
            ht = 0.0f; hfull = 0.0f; cfull = 0.0f; cb = 0.0f;
            ov = 0.0f; dv = 0.0f; ct = 0.0f;
        }

        const size_t base = (size_t)b * ((Ll + 1) * Hh) + (size_t)(t + 1) * Hh + j;
        out[0 * S_OUT + base] = ht;
        out[1 * S_OUT + base] = hfull;
        out[2 * S_OUT + base] = cfull;
        out[3 * S_OUT + base] = cb;
        out[4 * S_OUT + base] = ov;
        out[5 * S_OUT + base] = dv;

        __stcg(&g_h[nxt][b * 256 + j], ht);
        cprev = ct;

        if (t < Ll - 1) {
            __threadfence();           // every thread's g_h store -> gpu scope
            __syncthreads();           // all CTA threads fenced before arrive
            if (tid == 0) {
                atomicAdd(&g_cnt[t], 1u);
                while (*(volatile unsigned*)&g_cnt[t] < (unsigned)NCTA) {}
            }
            __syncthreads();           // release CTA; hs also safe to overwrite
        }
    }
}

// ---------------------------------------------------------------------------
// Launch
// ---------------------------------------------------------------------------
extern "C" void kernel_launch(void* const* d_in, const int* in_sizes, int n_in,
                              void* d_out, int out_size) {
    const float* x   = (const float*)d_in[0];   // (B, L, I)
    const float* dt  = (const float*)d_in[1];   // (B, L, 1)
    const int*   sl  = (const int*)  d_in[2];   // (B,)
    const float* Wx  = (const float*)d_in[3];   // (7H, I)
    const float* bx  = (const float*)d_in[4];   // (7H,)
    const float* Wh  = (const float*)d_in[5];   // (7H, H)
    const float* bh  = (const float*)d_in[6];   // (7H,)
    float* out = (float*)d_out;

    cudaFuncSetAttribute(scan_kernel,
                         cudaFuncAttributeMaxDynamicSharedMemorySize, SCAN_SMEM);

    init_kernel<<<(6 * Bb * Hh + 255) / 256, 256>>>(out);
    xg_gemm<<<dim3(Gg / 128, (Bb * Ll) / 128), 256>>>(x, Wx, bx);
    scan_kernel<<<NCTA, 128, SCAN_SMEM>>>(dt, sl, Wh, bh, out);
}

// round 10
// speedup vs baseline: 1.2039x; 1.2039x over previous
#include <cuda_runtime.h>
#include <cuda_bf16.h>
#include <cstdint>
#include <cstddef>

// ---------------------------------------------------------------------------
// CTLSTM: B=64, L=512, I=256, H=256, G=7H=1792
// Outputs: 6 planes, each (B, L+1, H) fp32, concatenated in d_out:
//   [h_decayed, h, c, c_bar, o, d]
// ---------------------------------------------------------------------------

constexpr int Bb = 64;
constexpr int Ll = 512;
constexpr int Ii = 256;
constexpr int Hh = 256;
constexpr int Gg = 7 * Hh;                 // 1792
constexpr int NCTA = 128;                  // scan grid (co-resident, <=148 SMs)
constexpr size_t S_OUT = (size_t)Bb * (Ll + 1) * Hh;   // 8,404,992

// Scan SMEM: Wh slice (56 rows x WPAD) + h tile (16 x WPAD) + k-reduction buf
constexpr int WPAD = 260;                  // 256 + 4 floats padding
constexpr int SCAN_SMEM = (56 * WPAD + 16 * WPAD + 128 * 8) * 4;  // 78,976 B

// Device scratch (no allocation allowed)
__device__ float    g_xg[(size_t)Bb * Ll * Gg];   // 224 MB
__device__ float    g_h[2][Bb * Hh];              // h double buffer
__device__ unsigned g_cnt[Ll];                    // per-step barrier counters

typedef unsigned long long u64;

// ---------------------------------------------------------------------------
// Packed fp32x2 helpers (Blackwell): 2 FMA per lane per instruction.
// ---------------------------------------------------------------------------
__device__ __forceinline__ u64 fma2(u64 a, u64 b, u64 c) {
    u64 d;
    asm("fma.rn.f32x2 %0, %1, %2, %3;" : "=l"(d) : "l"(a), "l"(b), "l"(c));
    return d;
}
__device__ __forceinline__ u64 dup2(float x) {
    u64 d;
    unsigned u = __float_as_uint(x);
    asm("mov.b64 %0, {%1, %2};" : "=l"(d) : "r"(u), "r"(u));
    return d;
}
__device__ __forceinline__ float lo2(u64 v) { return __uint_as_float((unsigned)v); }
__device__ __forceinline__ float hi2(u64 v) { return __uint_as_float((unsigned)(v >> 32)); }

// Barrier primitives (cooperative-groups grid.sync pattern)
__device__ __forceinline__ void red_release_add(unsigned* p, unsigned v) {
    asm volatile("red.release.gpu.global.add.u32 [%0], %1;" :: "l"(p), "r"(v) : "memory");
}
__device__ __forceinline__ unsigned ld_acquire(const unsigned* p) {
    unsigned v;
    asm volatile("ld.acquire.gpu.global.u32 %0, [%1];" : "=r"(v) : "l"(p) : "memory");
    return v;
}

// ---------------------------------------------------------------------------
// Init: zero barrier counters, h0, and the t=0 output rows (d_out is poisoned)
// ---------------------------------------------------------------------------
__global__ void init_kernel(float* __restrict__ out) {
    int i = blockIdx.x * blockDim.x + threadIdx.x;
    if (i < Ll) g_cnt[i] = 0u;
    if (i < Bb * Hh) g_h[0][i] = 0.0f;
    if (i < 6 * Bb * Hh) {
        int o = i / (Bb * Hh);
        int r = i % (Bb * Hh);
        int b = r >> 8;
        int j = r & 255;
        out[(size_t)o * S_OUT + (size_t)b * (Ll + 1) * Hh + j] = 0.0f;
    }
}

// ---------------------------------------------------------------------------
// Phase A: g_xg[m][g] = sum_k x[m][k] * Wx[g][k] + bx[g]
// M=32768, N=1792, K=256. 128x128 tiles, BK=16, double buffered,
// 8x8 microtile accumulated as 8x4 packed f32x2.
// ---------------------------------------------------------------------------
__global__ __launch_bounds__(256) void xg_gemm(const float* __restrict__ X,
                                               const float* __restrict__ W,
                                               const float* __restrict__ bx) {
    __shared__ float As[2][16][128];
    __shared__ float Bs[2][16][128];

    const int tid = threadIdx.x;
    const int tx  = tid & 15;
    const int ty  = tid >> 4;
    const int n0  = blockIdx.x * 128;
    const int m0  = blockIdx.y * 128;

    const int r0 = tid >> 2;   // 0..63
    const int r1 = r0 + 64;    // 64..127
    const int c4 = tid & 3;    // float4 index within a 16-wide k chunk

    u64 acc2[8][4];
#pragma unroll
    for (int i = 0; i < 8; ++i)
#pragma unroll
        for (int j = 0; j < 4; ++j) acc2[i][j] = 0ull;

    const float4* Xr0 = (const float4*)(X + (size_t)(m0 + r0) * Ii);
    const float4* Xr1 = (const float4*)(X + (size_t)(m0 + r1) * Ii);
    const float4* Wr0 = (const float4*)(W + (size_t)(n0 + r0) * Ii);
    const float4* Wr1 = (const float4*)(W + (size_t)(n0 + r1) * Ii);

    // preload kt = 0
    {
        float4 v0 = __ldg(Xr0 + c4);
        float4 v1 = __ldg(Xr1 + c4);
        float4 w0 = __ldg(Wr0 + c4);
        float4 w1 = __ldg(Wr1 + c4);
        As[0][c4 * 4 + 0][r0] = v0.x; As[0][c4 * 4 + 1][r0] = v0.y;
        As[0][c4 * 4 + 2][r0] = v0.z; As[0][c4 * 4 + 3][r0] = v0.w;
        As[0][c4 * 4 + 0][r1] = v1.x; As[0][c4 * 4 + 1][r1] = v1.y;
        As[0][c4 * 4 + 2][r1] = v1.z; As[0][c4 * 4 + 3][r1] = v1.w;
        Bs[0][c4 * 4 + 0][r0] = w0.x; Bs[0][c4 * 4 + 1][r0] = w0.y;
        Bs[0][c4 * 4 + 2][r0] = w0.z; Bs[0][c4 * 4 + 3][r0] = w0.w;
        Bs[0][c4 * 4 + 0][r1] = w1.x; Bs[0][c4 * 4 + 1][r1] = w1.y;
        Bs[0][c4 * 4 + 2][r1] = w1.z; Bs[0][c4 * 4 + 3][r1] = w1.w;
    }
    __syncthreads();

    int buf = 0;
    for (int kt = 0; kt < 16; ++kt) {
        float4 pv0, pv1, pw0, pw1;
        if (kt < 15) {
            int f4 = (kt + 1) * 4 + c4;
            pv0 = __ldg(Xr0 + f4);
            pv1 = __ldg(Xr1 + f4);
            pw0 = __ldg(Wr0 + f4);
            pw1 = __ldg(Wr1 + f4);
        }
#pragma unroll
        for (int kk = 0; kk < 16; ++kk) {
            float4 a0 = *(const float4*)&As[buf][kk][ty * 8];
            float4 a1 = *(const float4*)&As[buf][kk][ty * 8 + 4];
            ulonglong2 bp0 = *(const ulonglong2*)&Bs[buf][kk][tx * 8];
            ulonglong2 bp1 = *(const ulonglong2*)&Bs[buf][kk][tx * 8 + 4];
            u64 bu[4] = {bp0.x, bp0.y, bp1.x, bp1.y};
            float av[8] = {a0.x, a0.y, a0.z, a0.w, a1.x, a1.y, a1.z, a1.w};
#pragma unroll
            for (int i = 0; i < 8; ++i) {
                u64 ad = dup2(av[i]);
#pragma unroll
                for (int j = 0; j < 4; ++j)
                    acc2[i][j] = fma2(ad, bu[j], acc2[i][j]);
            }
        }
        if (kt < 15) {
            int nb = buf ^ 1;
            As[nb][c4 * 4 + 0][r0] = pv0.x; As[nb][c4 * 4 + 1][r0] = pv0.y;
            As[nb][c4 * 4 + 2][r0] = pv0.z; As[nb][c4 * 4 + 3][r0] = pv0.w;
            As[nb][c4 * 4 + 0][r1] = pv1.x; As[nb][c4 * 4 + 1][r1] = pv1.y;
            As[nb][c4 * 4 + 2][r1] = pv1.z; As[nb][c4 * 4 + 3][r1] = pv1.w;
            Bs[nb][c4 * 4 + 0][r0] = pw0.x; Bs[nb][c4 * 4 + 1][r0] = pw0.y;
            Bs[nb][c4 * 4 + 2][r0] = pw0.z; Bs[nb][c4 * 4 + 3][r0] = pw0.w;
            Bs[nb][c4 * 4 + 0][r1] = pw1.x; Bs[nb][c4 * 4 + 1][r1] = pw1.y;
            Bs[nb][c4 * 4 + 2][r1] = pw1.z; Bs[nb][c4 * 4 + 3][r1] = pw1.w;
        }
        __syncthreads();
        buf ^= 1;
    }

    float bxr[8];
#pragma unroll
    for (int j = 0; j < 8; ++j) bxr[j] = __ldg(bx + n0 + tx * 8 + j);

#pragma unroll
    for (int i = 0; i < 8; ++i) {
        size_t row = (size_t)(m0 + ty * 8 + i);
        float4 o0, o1;
        o0.x = lo2(acc2[i][0]) + bxr[0]; o0.y = hi2(acc2[i][0]) + bxr[1];
        o0.z = lo2(acc2[i][1]) + bxr[2]; o0.w = hi2(acc2[i][1]) + bxr[3];
        o1.x = lo2(acc2[i][2]) + bxr[4]; o1.y = hi2(acc2[i][2]) + bxr[5];
        o1.z = lo2(acc2[i][3]) + bxr[6]; o1.w = hi2(acc2[i][3]) + bxr[7];
        float4* cp = (float4*)(g_xg + row * Gg + n0 + tx * 8);
        cp[0] = o0;
        cp[1] = o1;
    }
}

// ---------------------------------------------------------------------------
// Scan helpers
// ---------------------------------------------------------------------------
__device__ __forceinline__ float sigmoidf_(float x) {
    return 1.0f / (1.0f + __expf(-x));
}
__device__ __forceinline__ float softplusf_(float x) {
    return (x > 20.0f) ? x : log1pf(__expf(x));
}

// ---------------------------------------------------------------------------
// Scan: 128 persistent CTAs x 256 threads. CTA = (16 batches) x (8 hidden j),
// k dimension split in half across thread groups (kh), reduced via SMEM.
// Wh slice (56 rows, padded stride 260) stays in SMEM for all 512 steps.
// ---------------------------------------------------------------------------
__global__ __launch_bounds__(256) void scan_kernel(
    const float* __restrict__ dt,        // (B, L)
    const int*   __restrict__ seq_lens,  // (B,)
    const float* __restrict__ Wh,        // (1792, 256)
    const float* __restrict__ bh,        // (1792,)
    float*       __restrict__ out)
{
    extern __shared__ float smem[];
    float* whs = smem;                          // [56][WPAD]
    float* hs  = smem + 56 * WPAD;              // [16][WPAD]
    float* red = smem + (56 + 16) * WPAD;       // [128][8]
    __shared__ int s_warp_max[8];

    const int tid  = threadIdx.x;
    const int cta  = blockIdx.x;
    const int jblk = cta & 31;          // 32 j-blocks of 8
    const int bblk = cta >> 5;          // 4 b-blocks of 16
    const int kh   = tid >> 7;          // 0 or 1 (k half)
    const int bi   = (tid >> 3) & 15;   // 0..15
    const int ji   = tid & 7;           // 0..7
    const int b    = bblk * 16 + bi;
    const int j    = jblk * 8 + ji;

    // Load the 56-row Wh slice into SMEM (rows g*256 + jblk*8 + jj).
    for (int idx = tid; idx < 56 * 64; idx += 256) {
        int row = idx >> 6;             // 0..55
        int cf  = idx & 63;             // float4 within row
        int g   = row >> 3;
        int jj  = row & 7;
        float4 v = __ldg((const float4*)(Wh + (size_t)(g * 256 + jblk * 8 + jj) * 256) + cf);
        *(float4*)(whs + row * WPAD + cf * 4) = v;
    }

    float bhr[7];
    if (kh == 0) {
#pragma unroll
        for (int g = 0; g < 7; ++g) bhr[g] = __ldg(bh + g * 256 + j);
    }

    const int my_len = __ldg(seq_lens + b);
    const int wmax   = __reduce_max_sync(0xffffffffu, my_len);
    if ((tid & 31) == 0) s_warp_max[tid >> 5] = wmax;
    __syncthreads();
    int cta_max = 0;
#pragma unroll
    for (int w = 0; w < 8; ++w) cta_max = max(cta_max, s_warp_max[w]);
    __syncthreads();

    const float* hp  = hs  + bi * WPAD + kh * 128;
    const float* wpb = whs + ji * WPAD + kh * 128;

    float cprev = 0.0f;

    for (int t = 0; t < Ll; ++t) {
        const int cur = t & 1;
        const int nxt = cur ^ 1;
        const bool active = (t < cta_max);

        // Load h tile (16 x 256) from g_h[cur] -> hs, bypassing L1 (__ldcg):
        // same addresses recur every other step and L1 is not coherent.
        if (active) {
            const float4* src = (const float4*)(g_h[cur] + bblk * 16 * 256);
#pragma unroll
            for (int i = 0; i < 4; ++i) {
                int idx = tid + i * 256;            // 0..1023
                int row = idx >> 6;
                int cf  = idx & 63;
                float4 v = __ldcg(src + row * 64 + cf);
                *(float4*)(hs + row * WPAD + cf * 4) = v;
            }
        }

        // Prefetch xg gates + dt for this step (hidden under the dot product).
        float xgv[7] = {0, 0, 0, 0, 0, 0, 0};
        float dtv = 0.0f;
        if (kh == 0 && t < wmax) {
            const float* xp = g_xg + ((size_t)b * Ll + t) * Gg + j;
#pragma unroll
            for (int g = 0; g < 7; ++g) xgv[g] = __ldg(xp + g * 256);
            dtv = __ldg(dt + b * Ll + t);
        }

        __syncthreads();   // hs visible

        float acc[7] = {0, 0, 0, 0, 0, 0, 0};
        if (t < wmax) {
            u64 acc2[7] = {0, 0, 0, 0, 0, 0, 0};
#pragma unroll 2
            for (int k = 0; k < 128; k += 4) {
                const ulonglong2 hv = *(const ulonglong2*)(hp + k);
#pragma unroll
                for (int g = 0; g < 7; ++g) {
                    const ulonglong2 wv = *(const ulonglong2*)(wpb + g * (8 * WPAD) + k);
                    acc2[g] = fma2(hv.x, wv.x, acc2[g]);
                    acc2[g] = fma2(hv.y, wv.y, acc2[g]);
                }
            }
#pragma unroll
            for (int g = 0; g < 7; ++g) acc[g] = lo2(acc2[g]) + hi2(acc2[g]);
        }

        // Reduce the two k-halves: kh=1 writes partials, kh=0 accumulates.
        if (kh == 1) {
            float* rp = red + (tid - 128) * 8;
#pragma unroll
            for (int g = 0; g < 7; ++g) rp[g] = acc[g];
        }
        __syncthreads();

        float ht = 0.f, hfull = 0.f, cfull = 0.f, cb = 0.f, ov = 0.f, dv = 0.f;
        if (kh == 0) {
            const float* rp = red + tid * 8;
#pragma unroll
            for (int g = 0; g < 7; ++g) acc[g] += rp[g];

            // Gates. split order: i, f, z, o, d, ib, fb
            float iv  = sigmoidf_(acc[0] + xgv[0] + bhr[0]);
            float fv  = sigmoidf_(acc[1] + xgv[1] + bhr[1]);
            float zv  = tanhf   (acc[2] + xgv[2] + bhr[2]);
            ov        = sigmoidf_(acc[3] + xgv[3] + bhr[3]);
            dv        = softplusf_(acc[4] + xgv[4] + bhr[4]);
            float ibv = sigmoidf_(acc[5] + xgv[5] + bhr[5]);
            float fbv = sigmoidf_(acc[6] + xgv[6] + bhr[6]);

            cfull = fv * cprev + iv * zv;
            hfull = ov * tanhf(cfull);
            cb    = fbv * cprev + ibv * zv;
            float ct = cb + (cfull - cb) * __expf(-dv * dtv);
            ht    = ov * tanhf(ct);

            if (t >= my_len) {          // masked: outputs and carry are zero
                ht = 0.0f; hfull = 0.0f; cfull = 0.0f; cb = 0.0f;
                ov = 0.0f; dv = 0.0f; ct = 0.0f;
            }
            __stcg(&g_h[nxt][b * 256 + j], ht);
            cprev = ct;
        }

        const size_t base = (size_t)b * ((Ll + 1) * Hh) + (size_t)(t + 1) * Hh + j;

        if (t < Ll - 1) {
            __syncthreads();            // all g_h stores issued CTA-wide
            if (tid == 0) {
                __threadfence();        // push them to gpu scope (tid0 only)
                red_release_add(&g_cnt[t], 1u);
            }
            // Output stores have no cross-CTA consumer: overlap the wait.
            if (kh == 0) {
                out[0 * S_OUT + base] = ht;
                out[1 * S_OUT + base] = hfull;
                out[2 * S_OUT + base] = cfull;
                out[3 * S_OUT + base] = cb;
                out[4 * S_OUT + base] = ov;
                out[5 * S_OUT + base] = dv;
            }
            if (tid == 0) {
                while (ld_acquire(&g_cnt[t]) < (unsigned)NCTA) {}
            }
            __syncthreads();            // release CTA; hs safe to overwrite
        } else {
            if (kh == 0) {
                out[0 * S_OUT + base] = ht;
                out[1 * S_OUT + base] = hfull;
                out[2 * S_OUT + base] = cfull;
                out[3 * S_OUT + base] = cb;
                out[4 * S_OUT + base] = ov;
                out[5 * S_OUT + base] = dv;
            }
        }
    }
}

// ---------------------------------------------------------------------------
// Launch
// ---------------------------------------------------------------------------
extern "C" void kernel_launch(void* const* d_in, const int* in_sizes, int n_in,
                              void* d_out, int out_size) {
    const float* x   = (const float*)d_in[0];   // (B, L, I)
    const float* dt  = (const float*)d_in[1];   // (B, L, 1)
    const int*   sl  = (const int*)  d_in[2];   // (B,)
    const float* Wx  = (const float*)d_in[3];   // (7H, I)
    const float* bx  = (const float*)d_in[4];   // (7H,)
    const float* Wh  = (const float*)d_in[5];   // (7H, H)
    const float* bh  = (const float*)d_in[6];   // (7H,)
    float* out = (float*)d_out;

    cudaFuncSetAttribute(scan_kernel,
                         cudaFuncAttributeMaxDynamicSharedMemorySize, SCAN_SMEM);

    init_kernel<<<(6 * Bb * Hh + 255) / 256, 256>>>(out);
    xg_gemm<<<dim3(Gg / 128, (Bb * Ll) / 128), 256>>>(x, Wx, bx);
    scan_kernel<<<NCTA, 256, SCAN_SMEM>>>(dt, sl, Wh, bh, out);
}

// round 11
// speedup vs baseline: 1.9008x; 1.5788x over previous
#include <cuda_runtime.h>
#include <cuda_bf16.h>
#include <cstdint>
#include <cstddef>

// ---------------------------------------------------------------------------
// CTLSTM: B=64, L=512, I=256, H=256, G=7H=1792
// Outputs: 6 planes, each (B, L+1, H) fp32, concatenated in d_out:
//   [h_decayed, h, c, c_bar, o, d]
// ---------------------------------------------------------------------------

constexpr int Bb = 64;
constexpr int Ll = 512;
constexpr int Ii = 256;
constexpr int Hh = 256;
constexpr int Gg = 7 * Hh;                 // 1792
constexpr int NCTA = 128;                  // scan grid (co-resident, <=148 SMs)
constexpr int NGRP = 8;                    // independent batch groups
constexpr int GCTA = 16;                   // CTAs per group (j-blocks)
constexpr int BPG  = 8;                    // batches per group
constexpr int JPC  = 16;                   // j values per CTA
constexpr size_t S_OUT = (size_t)Bb * (Ll + 1) * Hh;   // 8,404,992

// Scan SMEM (floats): weights [7][16][WROW] + h tile [8][WROW] + red [256][RSTR]
constexpr int WROW = 260;                  // 16B-aligned row, 2-cycle LDS.128
constexpr int RSTR = 34;                   // reduction stride (conflict-free reads)
constexpr int SM_HS  = 7 * JPC * WROW;             // 29120
constexpr int SM_RED = SM_HS + BPG * WROW;         // 31200
constexpr int SCAN_SMEM = (SM_RED + 256 * RSTR) * 4;  // 159,616 B

// Device scratch (no allocation allowed)
__device__ float    g_xg[(size_t)Bb * Ll * Gg];   // 224 MB
__device__ float    g_h[2][Bb * Hh];              // h double buffer
__device__ unsigned g_cnt[NGRP][Ll];              // per-group per-step counters

typedef unsigned long long u64;

// ---------------------------------------------------------------------------
// Packed fp32x2 helpers (Blackwell): 2 fp32 FMA per lane per instruction.
// ---------------------------------------------------------------------------
__device__ __forceinline__ u64 fma2(u64 a, u64 b, u64 c) {
    u64 d;
    asm("fma.rn.f32x2 %0, %1, %2, %3;" : "=l"(d) : "l"(a), "l"(b), "l"(c));
    return d;
}
__device__ __forceinline__ u64 dup2(float x) {
    u64 d;
    unsigned u = __float_as_uint(x);
    asm("mov.b64 %0, {%1, %2};" : "=l"(d) : "r"(u), "r"(u));
    return d;
}
__device__ __forceinline__ float lo2(u64 v) { return __uint_as_float((unsigned)v); }
__device__ __forceinline__ float hi2(u64 v) { return __uint_as_float((unsigned)(v >> 32)); }

// Barrier primitives
__device__ __forceinline__ void red_release_add(unsigned* p, unsigned v) {
    asm volatile("red.release.gpu.global.add.u32 [%0], %1;" :: "l"(p), "r"(v) : "memory");
}
__device__ __forceinline__ unsigned ld_acquire(const unsigned* p) {
    unsigned v;
    asm volatile("ld.acquire.gpu.global.u32 %0, [%1];" : "=r"(v) : "l"(p) : "memory");
    return v;
}

// ---------------------------------------------------------------------------
// Init: zero barrier counters, h0, and the t=0 output rows (d_out is poisoned)
// ---------------------------------------------------------------------------
__global__ void init_kernel(float* __restrict__ out) {
    int i = blockIdx.x * blockDim.x + threadIdx.x;
    if (i < NGRP * Ll) ((unsigned*)g_cnt)[i] = 0u;
    if (i < Bb * Hh) g_h[0][i] = 0.0f;
    if (i < 6 * Bb * Hh) {
        int o = i / (Bb * Hh);
        int r = i % (Bb * Hh);
        int b = r >> 8;
        int j = r & 255;
        out[(size_t)o * S_OUT + (size_t)b * (Ll + 1) * Hh + j] = 0.0f;
    }
}

// ---------------------------------------------------------------------------
// Phase A: g_xg[m][g] = sum_k x[m][k] * Wx[g][k] + bx[g]
// M=32768, N=1792, K=256. 128x128 tiles, BK=16, double buffered, f32x2 FMAs.
// ---------------------------------------------------------------------------
__global__ __launch_bounds__(256) void xg_gemm(const float* __restrict__ X,
                                               const float* __restrict__ W,
                                               const float* __restrict__ bx) {
    __shared__ float As[2][16][128];
    __shared__ float Bs[2][16][128];

    const int tid = threadIdx.x;
    const int tx  = tid & 15;
    const int ty  = tid >> 4;
    const int n0  = blockIdx.x * 128;
    const int m0  = blockIdx.y * 128;

    const int r0 = tid >> 2;   // 0..63
    const int r1 = r0 + 64;    // 64..127
    const int c4 = tid & 3;    // float4 index within a 16-wide k chunk

    u64 acc2[8][4];
#pragma unroll
    for (int i = 0; i < 8; ++i)
#pragma unroll
        for (int j = 0; j < 4; ++j) acc2[i][j] = 0ull;

    const float4* Xr0 = (const float4*)(X + (size_t)(m0 + r0) * Ii);
    const float4* Xr1 = (const float4*)(X + (size_t)(m0 + r1) * Ii);
    const float4* Wr0 = (const float4*)(W + (size_t)(n0 + r0) * Ii);
    const float4* Wr1 = (const float4*)(W + (size_t)(n0 + r1) * Ii);

    {
        float4 v0 = __ldg(Xr0 + c4);
        float4 v1 = __ldg(Xr1 + c4);
        float4 w0 = __ldg(Wr0 + c4);
        float4 w1 = __ldg(Wr1 + c4);
        As[0][c4 * 4 + 0][r0] = v0.x; As[0][c4 * 4 + 1][r0] = v0.y;
        As[0][c4 * 4 + 2][r0] = v0.z; As[0][c4 * 4 + 3][r0] = v0.w;
        As[0][c4 * 4 + 0][r1] = v1.x; As[0][c4 * 4 + 1][r1] = v1.y;
        As[0][c4 * 4 + 2][r1] = v1.z; As[0][c4 * 4 + 3][r1] = v1.w;
        Bs[0][c4 * 4 + 0][r0] = w0.x; Bs[0][c4 * 4 + 1][r0] = w0.y;
        Bs[0][c4 * 4 + 2][r0] = w0.z; Bs[0][c4 * 4 + 3][r0] = w0.w;
        Bs[0][c4 * 4 + 0][r1] = w1.x; Bs[0][c4 * 4 + 1][r1] = w1.y;
        Bs[0][c4 * 4 + 2][r1] = w1.z; Bs[0][c4 * 4 + 3][r1] = w1.w;
    }
    __syncthreads();

    int buf = 0;
    for (int kt = 0; kt < 16; ++kt) {
        float4 pv0, pv1, pw0, pw1;
        if (kt < 15) {
            int f4 = (kt + 1) * 4 + c4;
            pv0 = __ldg(Xr0 + f4);
            pv1 = __ldg(Xr1 + f4);
            pw0 = __ldg(Wr0 + f4);
            pw1 = __ldg(Wr1 + f4);
        }
#pragma unroll
        for (int kk = 0; kk < 16; ++kk) {
            float4 a0 = *(const float4*)&As[buf][kk][ty * 8];
            float4 a1 = *(const float4*)&As[buf][kk][ty * 8 + 4];
            ulonglong2 bp0 = *(const ulonglong2*)&Bs[buf][kk][tx * 8];
            ulonglong2 bp1 = *(const ulonglong2*)&Bs[buf][kk][tx * 8 + 4];
            u64 bu[4] = {bp0.x, bp0.y, bp1.x, bp1.y};
            float av[8] = {a0.x, a0.y, a0.z, a0.w, a1.x, a1.y, a1.z, a1.w};
#pragma unroll
            for (int i = 0; i < 8; ++i) {
                u64 ad = dup2(av[i]);
#pragma unroll
                for (int j = 0; j < 4; ++j)
                    acc2[i][j] = fma2(ad, bu[j], acc2[i][j]);
            }
        }
        if (kt < 15) {
            int nb = buf ^ 1;
            As[nb][c4 * 4 + 0][r0] = pv0.x; As[nb][c4 * 4 + 1][r0] = pv0.y;
            As[nb][c4 * 4 + 2][r0] = pv0.z; As[nb][c4 * 4 + 3][r0] = pv0.w;
            As[nb][c4 * 4 + 0][r1] = pv1.x; As[nb][c4 * 4 + 1][r1] = pv1.y;
            As[nb][c4 * 4 + 2][r1] = pv1.z; As[nb][c4 * 4 + 3][r1] = pv1.w;
            Bs[nb][c4 * 4 + 0][r0] = pw0.x; Bs[nb][c4 * 4 + 1][r0] = pw0.y;
            Bs[nb][c4 * 4 + 2][r0] = pw0.z; Bs[nb][c4 * 4 + 3][r0] = pw0.w;
            Bs[nb][c4 * 4 + 0][r1] = pw1.x; Bs[nb][c4 * 4 + 1][r1] = pw1.y;
            Bs[nb][c4 * 4 + 2][r1] = pw1.z; Bs[nb][c4 * 4 + 3][r1] = pw1.w;
        }
        __syncthreads();
        buf ^= 1;
    }

    float bxr[8];
#pragma unroll
    for (int j = 0; j < 8; ++j) bxr[j] = __ldg(bx + n0 + tx * 8 + j);

#pragma unroll
    for (int i = 0; i < 8; ++i) {
        size_t row = (size_t)(m0 + ty * 8 + i);
        float4 o0, o1;
        o0.x = lo2(acc2[i][0]) + bxr[0]; o0.y = hi2(acc2[i][0]) + bxr[1];
        o0.z = lo2(acc2[i][1]) + bxr[2]; o0.w = hi2(acc2[i][1]) + bxr[3];
        o1.x = lo2(acc2[i][2]) + bxr[4]; o1.y = hi2(acc2[i][2]) + bxr[5];
        o1.z = lo2(acc2[i][3]) + bxr[6]; o1.w = hi2(acc2[i][3]) + bxr[7];
        float4* cp = (float4*)(g_xg + row * Gg + n0 + tx * 8);
        cp[0] = o0;
        cp[1] = o1;
    }
}

// ---------------------------------------------------------------------------
// Scan helpers
// ---------------------------------------------------------------------------
__device__ __forceinline__ float sigmoidf_(float x) {
    return 1.0f / (1.0f + __expf(-x));
}
__device__ __forceinline__ float softplusf_(float x) {
    return (x > 20.0f) ? x : log1pf(__expf(x));
}

// ---------------------------------------------------------------------------
// Scan: 128 persistent CTAs = 8 batch-groups x 16 j-blocks. CTA covers
// 8 batches x 16 j. 256 threads = (bg:2 x ji:16) x (kq:8 warps); each thread
// batch-blocks 4 batches so weights are read from SMEM exactly once per step.
// Only the 16 CTAs of a batch-group synchronize per step.
// ---------------------------------------------------------------------------
__global__ __launch_bounds__(256, 1) void scan_kernel(
    const float* __restrict__ dt,        // (B, L)
    const int*   __restrict__ seq_lens,  // (B,)
    const float* __restrict__ Wh,        // (1792, 256)
    const float* __restrict__ bh,        // (1792,)
    float*       __restrict__ out)
{
    extern __shared__ float smem[];
    float* whs = smem;                   // [7][16][WROW]
    float* hs  = smem + SM_HS;           // [8][WROW]
    float* red = smem + SM_RED;          // [256][RSTR]
    __shared__ int s_len[BPG];

    const int tid  = threadIdx.x;
    const int grp  = blockIdx.x >> 4;    // 0..7 batch group
    const int jblk = blockIdx.x & 15;    // 0..15 j block
    const int b0   = grp * BPG;
    const int j0   = jblk * JPC;

    const int kq   = tid >> 5;           // warp = k slice (0..7)
    const int lane = tid & 31;
    const int bg   = lane >> 4;          // 0..1 (batch half)
    const int ji   = lane & 15;          // 0..15

    // Load weight slice: Wh rows g*256 + j0 + jj, 7 gates x 16 j x 256 k.
    for (int idx = tid; idx < 7 * JPC * 64; idx += 256) {
        int row = idx >> 6;              // 0..111 (= g*16 + jj)
        int cf  = idx & 63;
        int g   = row >> 4;
        int jj  = row & 15;
        float4 v = __ldg((const float4*)(Wh + (size_t)(g * 256 + j0 + jj) * 256) + cf);
        *(float4*)(whs + row * WROW + cf * 4) = v;
    }

    if (tid < BPG) s_len[tid] = __ldg(seq_lens + b0 + tid);
    __syncthreads();
    int cta_max = 0;
#pragma unroll
    for (int i = 0; i < BPG; ++i) cta_max = max(cta_max, s_len[i]);

    // Reader (finalize) role: tid<128, one (b_local, ji) pair each.
    const bool isrd   = (tid < 128);
    const int  bl     = tid >> 4;        // 0..7 (reader batch index)
    const int  jr     = tid & 15;        // 0..15 (reader j index)
    const int  rb     = b0 + bl;
    const int  rj     = j0 + jr;
    const int  my_len = isrd ? s_len[bl] : 0;

    float bhr[7];
    if (isrd) {
#pragma unroll
        for (int g = 0; g < 7; ++g) bhr[g] = __ldg(bh + g * 256 + rj);
    }

    const float* wbase = whs + ji * WROW;
    const float* hbase = hs + bg * 4 * WROW;
    float cprev = 0.0f;

    for (int t = 0; t < cta_max; ++t) {
        const int cur = t & 1;
        const int nxt = cur ^ 1;

        // Load h tile (8 x 256) from L2 (__ldcg: cross-CTA producer).
        {
            const float4* src = (const float4*)(g_h[cur] + b0 * Hh);
#pragma unroll
            for (int i = 0; i < 2; ++i) {
                int idx = tid + i * 256;          // 0..511
                int row = idx >> 6;
                int cf  = idx & 63;
                float4 v = __ldcg(src + idx);
                *(float4*)(hs + row * WROW + cf * 4) = v;
            }
        }

        // Prefetch xg gates + dt (readers only; hidden under the dot).
        float xgv[7] = {0, 0, 0, 0, 0, 0, 0};
        float dtv = 0.0f;
        if (isrd && t < my_len) {
            const float* xp = g_xg + ((size_t)rb * Ll + t) * Gg + rj;
#pragma unroll
            for (int g = 0; g < 7; ++g) xgv[g] = __ldg(xp + g * 256);
            dtv = __ldg(dt + rb * Ll + t);
        }

        __syncthreads();   // hs visible

        // Dot: thread covers 4 batches (bg*4..bg*4+3), j=ji, k-slice kq*32+32.
        u64 acc2[7][4];
#pragma unroll
        for (int g = 0; g < 7; ++g)
#pragma unroll
            for (int bb = 0; bb < 4; ++bb) acc2[g][bb] = 0ull;

#pragma unroll
        for (int kc = 0; kc < 8; ++kc) {
            const int k = kq * 32 + kc * 4;
            ulonglong2 hv[4];
#pragma unroll
            for (int bb = 0; bb < 4; ++bb)
                hv[bb] = *(const ulonglong2*)(hbase + bb * WROW + k);
#pragma unroll
            for (int g = 0; g < 7; ++g) {
                const ulonglong2 wv = *(const ulonglong2*)(wbase + g * (JPC * WROW) + k);
#pragma unroll
                for (int bb = 0; bb < 4; ++bb) {
                    acc2[g][bb] = fma2(hv[bb].x, wv.x, acc2[g][bb]);
                    acc2[g][bb] = fma2(hv[bb].y, wv.y, acc2[g][bb]);
                }
            }
        }

        // Write 28 partials as 14 float2 (2-cycle STS.64, stride RSTR words).
        {
            float vals[28];
#pragma unroll
            for (int bb = 0; bb < 4; ++bb)
#pragma unroll
                for (int g = 0; g < 7; ++g)
                    vals[bb * 7 + g] = lo2(acc2[g][bb]) + hi2(acc2[g][bb]);
            float2* rp2 = (float2*)(red + tid * RSTR);
#pragma unroll
            for (int k2 = 0; k2 < 14; ++k2)
                rp2[k2] = make_float2(vals[2 * k2], vals[2 * k2 + 1]);
        }
        __syncthreads();

        float ht = 0.f, hfull = 0.f, cfull = 0.f, cb = 0.f, ov = 0.f, dv = 0.f;
        if (isrd) {
            const int rbg = bl >> 2;      // 0..1
            const int rbb = bl & 3;       // 0..3
            float acc[7] = {0, 0, 0, 0, 0, 0, 0};
#pragma unroll
            for (int q = 0; q < 8; ++q) {
                const float* rp = red + (q * 32 + rbg * 16 + jr) * RSTR + rbb * 7;
#pragma unroll
                for (int g = 0; g < 7; ++g) acc[g] += rp[g];
            }

            // Gates. split order: i, f, z, o, d, ib, fb
            float iv  = sigmoidf_(acc[0] + xgv[0] + bhr[0]);
            float fv  = sigmoidf_(acc[1] + xgv[1] + bhr[1]);
            float zv  = tanhf   (acc[2] + xgv[2] + bhr[2]);
            ov        = sigmoidf_(acc[3] + xgv[3] + bhr[3]);
            dv        = softplusf_(acc[4] + xgv[4] + bhr[4]);
            float ibv = sigmoidf_(acc[5] + xgv[5] + bhr[5]);
            float fbv = sigmoidf_(acc[6] + xgv[6] + bhr[6]);

            cfull = fv * cprev + iv * zv;
            hfull = ov * tanhf(cfull);
            cb    = fbv * cprev + ibv * zv;
            float ct = cb + (cfull - cb) * __expf(-dv * dtv);
            ht    = ov * tanhf(ct);

            if (t >= my_len) {            // masked: outputs and carry are zero
                ht = 0.0f; hfull = 0.0f; cfull = 0.0f; cb = 0.0f;
                ov = 0.0f; dv = 0.0f; ct = 0.0f;
            }
            __stcg(&g_h[nxt][rb * Hh + rj], ht);
            cprev = ct;
        }

        __syncthreads();                  // all h stores issued CTA-wide
        const bool dobar = (t < cta_max - 1);
        if (dobar && tid == 0) {
            __threadfence();              // push h stores to gpu scope
            red_release_add(&g_cnt[grp][t], 1u);
        }
        // Output stores have no cross-CTA consumer: overlap the spin.
        if (isrd) {
            const size_t base = (size_t)rb * ((Ll + 1) * Hh) + (size_t)(t + 1) * Hh + rj;
            out[0 * S_OUT + base] = ht;
            out[1 * S_OUT + base] = hfull;
            out[2 * S_OUT + base] = cfull;
            out[3 * S_OUT + base] = cb;
            out[4 * S_OUT + base] = ov;
            out[5 * S_OUT + base] = dv;
        }
        if (dobar && tid == 0) {
            while (ld_acquire(&g_cnt[grp][t]) < (unsigned)GCTA) {}
        }
        __syncthreads();                  // release CTA; hs safe to overwrite
    }

    // Tail: all batches in this group are past seq_len — outputs are zeros.
    for (int t = cta_max; t < Ll; ++t) {
        if (isrd) {
            const size_t base = (size_t)rb * ((Ll + 1) * Hh) + (size_t)(t + 1) * Hh + rj;
#pragma unroll
            for (int p = 0; p < 6; ++p) out[p * S_OUT + base] = 0.0f;
        }
    }
}

// ---------------------------------------------------------------------------
// Launch
// ---------------------------------------------------------------------------
extern "C" void kernel_launch(void* const* d_in, const int* in_sizes, int n_in,
                              void* d_out, int out_size) {
    const float* x   = (const float*)d_in[0];   // (B, L, I)
    const float* dt  = (const float*)d_in[1];   // (B, L, 1)
    const int*   sl  = (const int*)  d_in[2];   // (B,)
    const float* Wx  = (const float*)d_in[3];   // (7H, I)
    const float* bx  = (const float*)d_in[4];   // (7H,)
    const float* Wh  = (const float*)d_in[5];   // (7H, H)
    const float* bh  = (const float*)d_in[6];   // (7H,)
    float* out = (float*)d_out;

    cudaFuncSetAttribute(scan_kernel,
                         cudaFuncAttributeMaxDynamicSharedMemorySize, SCAN_SMEM);

    init_kernel<<<(6 * Bb * Hh + 255) / 256, 256>>>(out);
    xg_gemm<<<dim3(Gg / 128, (Bb * Ll) / 128), 256>>>(x, Wx, bx);
    scan_kernel<<<NCTA, 256, SCAN_SMEM>>>(dt, sl, Wh, bh, out);
}